// round 1
// baseline (speedup 1.0000x reference)
#include <cuda_runtime.h>
#include <math.h>

// ---------------------------------------------------------------------------
// EfficientVSR windowed cross-attention, fully fused: one CTA per 8x8 window.
// B=8, C=128, H=W=256, ws=8, heads=4, hd=32.
// Phases (all in smem): load windows -> Q/K/V proj GEMMs -> RoPE -> per-head
// attention (S=QK^T, softmax, O=SV) -> Wo GEMM -> LayerNorm + residual -> store.
// ---------------------------------------------------------------------------

constexpr int TPB   = 256;
constexpr int CH    = 128;
constexpr int IMG_H = 256;
constexpr int IMG_W = 256;
constexpr int WSZ   = 8;
constexpr int NTOK  = 64;     // ws*ws
constexpr int NH    = 4;
constexpr int HD    = 32;
constexpr int XP    = 129;    // padded row stride for [64][128] token-major tiles
constexpr int WPAD  = 132;    // weight tile row stride: Wt[cc][d], cc in [0,32)
constexpr int SPD   = 65;     // padded row stride for S [64][64]

// smem layout (floats)
constexpr int OFF_XQ = 0;                      // temporal window (kept for residual)
constexpr int OFF_Q  = OFF_XQ + NTOK * XP;     // Q, later final output
constexpr int OFF_K  = OFF_Q  + NTOK * XP;
constexpr int OFF_V  = OFF_K  + NTOK * XP;
constexpr int OFF_P  = OFF_V  + NTOK * XP;     // spatial window, later attn out O
constexpr int OFF_WT = OFF_P  + NTOK * XP;     // staged weight tile 32x128 (+pad)
constexpr int OFF_S  = OFF_WT + 32 * WPAD;     // attention scores 64x64 (+pad)
constexpr int SMEM_FLOATS = OFF_S + NTOK * SPD;
constexpr int SMEM_BYTES  = SMEM_FLOATS * 4;   // 198656 B

// 64x128 = X[64][128] @ W[128][128]^T  (out[t][d] = sum_c X[t][c]*W[d][c])
// Thread (ty,tx) in 16x16 grid computes rows t0..t0+3, cols {4tx..4tx+3, 64+4tx..64+4tx+3}.
__device__ __forceinline__ void gemm_64x128x128(
    float* sm, int srcOff, const float* __restrict__ Wg, int dstOff, int tid)
{
    const int ty = tid >> 4;
    const int tx = tid & 15;
    const int t0 = ty << 2;
    const int dA = tx << 2;        // cols dA..dA+3
    const int dB = 64 + (tx << 2); // cols dB..dB+3

    float acc[4][8];
#pragma unroll
    for (int i = 0; i < 4; i++)
#pragma unroll
        for (int j = 0; j < 8; j++) acc[i][j] = 0.0f;

    for (int c0 = 0; c0 < CH; c0 += 32) {
        // stage weight tile: Wt[cc][d] = Wg[d*128 + c0 + cc]  (global reads coalesced)
#pragma unroll
        for (int k = 0; k < 16; k++) {                 // 4096 elems / 256 threads
            int i  = tid + k * TPB;
            int d  = i >> 5;
            int cc = i & 31;
            sm[OFF_WT + cc * WPAD + d] = Wg[(d << 7) + c0 + cc];
        }
        __syncthreads();

#pragma unroll 8
        for (int cc = 0; cc < 32; cc++) {
            const int xb = srcOff + t0 * XP + c0 + cc;
            float x0 = sm[xb];
            float x1 = sm[xb + XP];
            float x2 = sm[xb + 2 * XP];
            float x3 = sm[xb + 3 * XP];
            const float4 wa = *reinterpret_cast<const float4*>(&sm[OFF_WT + cc * WPAD + dA]);
            const float4 wb = *reinterpret_cast<const float4*>(&sm[OFF_WT + cc * WPAD + dB]);
            float w[8] = {wa.x, wa.y, wa.z, wa.w, wb.x, wb.y, wb.z, wb.w};
#pragma unroll
            for (int j = 0; j < 8; j++) {
                acc[0][j] = fmaf(x0, w[j], acc[0][j]);
                acc[1][j] = fmaf(x1, w[j], acc[1][j]);
                acc[2][j] = fmaf(x2, w[j], acc[2][j]);
                acc[3][j] = fmaf(x3, w[j], acc[3][j]);
            }
        }
        __syncthreads();
    }

#pragma unroll
    for (int i = 0; i < 4; i++) {
#pragma unroll
        for (int j = 0; j < 4; j++) {
            sm[dstOff + (t0 + i) * XP + dA + j] = acc[i][j];
            sm[dstOff + (t0 + i) * XP + dB + j] = acc[i][4 + j];
        }
    }
}

__global__ void __launch_bounds__(TPB, 1)
evsr_kernel(const float* __restrict__ tf, const float* __restrict__ sf,
            const float* __restrict__ Wq, const float* __restrict__ Wk,
            const float* __restrict__ Wv, const float* __restrict__ Wo,
            const float* __restrict__ lnw, const float* __restrict__ lnb,
            float* __restrict__ out)
{
    extern __shared__ float sm[];
    const int tid = threadIdx.x;
    const int blk = blockIdx.x;
    const int b   = blk >> 10;         // 1024 windows per image (32x32)
    const int wy  = (blk >> 5) & 31;
    const int wx  = blk & 31;
    // element offset of (c=0, y=wy*8, x=wx*8) in [B,C,H,W]
    const int base = ((b * CH) << 16) + ((wy * WSZ) << 8) + (wx * WSZ);

    // ---- Phase 1: load temporal window -> XQ, spatial window -> P ----
#pragma unroll
    for (int k = 0; k < 32; k++) {     // 8192 elems / 256 threads
        int idx = tid + k * TPB;
        int c = idx >> 6;
        int t = idx & 63;
        int g = base + (c << 16) + ((t >> 3) << 8) + (t & 7);
        sm[OFF_XQ + t * XP + c] = tf[g];
        sm[OFF_P  + t * XP + c] = sf[g];
    }
    __syncthreads();

    // ---- Phase 2: projections ----
    gemm_64x128x128(sm, OFF_XQ, Wq, OFF_Q, tid);
    gemm_64x128x128(sm, OFF_P,  Wk, OFF_K, tid);
    gemm_64x128x128(sm, OFF_P,  Wv, OFF_V, tid);
    __syncthreads();

    // ---- Phase 3: 2D RoPE on Q and K ----
    // token t=(py,px): angle = (py+px) * 10000^(-i/16), i in [0,16) per head
#pragma unroll
    for (int k = 0; k < 16; k++) {     // 64 tok * 4 heads * 16 pairs / 256 threads
        int idx = tid + k * TPB;
        int t = idx >> 6;
        int h = (idx >> 4) & 3;
        int i = idx & 15;
        int py = t >> 3, px = t & 7;
        float freq = powf(10000.0f, -(float)i * (1.0f / 16.0f));
        float ang = (float)(py + px) * freq;
        float sv, cv;
        sincosf(ang, &sv, &cv);
        int c1 = h * HD + i;
        int c2 = c1 + 16;
        float q1 = sm[OFF_Q + t * XP + c1], q2 = sm[OFF_Q + t * XP + c2];
        sm[OFF_Q + t * XP + c1] = q1 * cv - q2 * sv;
        sm[OFF_Q + t * XP + c2] = q1 * sv + q2 * cv;
        float k1 = sm[OFF_K + t * XP + c1], k2 = sm[OFF_K + t * XP + c2];
        sm[OFF_K + t * XP + c1] = k1 * cv - k2 * sv;
        sm[OFF_K + t * XP + c2] = k1 * sv + k2 * cv;
    }
    __syncthreads();

    // ---- Phase 4: attention per head ----
    const float scale = 0.17677669529663687f;  // 1/sqrt(32)
    const int ty = tid >> 4, tx = tid & 15;
    for (int h = 0; h < NH; h++) {
        const int hc = h * HD;
        // S = Q K^T * scale : 64x64, 4x4 tile per thread
        {
            const int t0 = ty << 2, m0 = tx << 2;
            float a[4][4];
#pragma unroll
            for (int i = 0; i < 4; i++)
#pragma unroll
                for (int j = 0; j < 4; j++) a[i][j] = 0.0f;
#pragma unroll 8
            for (int k = 0; k < HD; k++) {
                float q0 = sm[OFF_Q + (t0 + 0) * XP + hc + k];
                float q1 = sm[OFF_Q + (t0 + 1) * XP + hc + k];
                float q2 = sm[OFF_Q + (t0 + 2) * XP + hc + k];
                float q3 = sm[OFF_Q + (t0 + 3) * XP + hc + k];
                float c0 = sm[OFF_K + (m0 + 0) * XP + hc + k];
                float c1 = sm[OFF_K + (m0 + 1) * XP + hc + k];
                float c2 = sm[OFF_K + (m0 + 2) * XP + hc + k];
                float c3 = sm[OFF_K + (m0 + 3) * XP + hc + k];
                a[0][0] = fmaf(q0, c0, a[0][0]); a[0][1] = fmaf(q0, c1, a[0][1]);
                a[0][2] = fmaf(q0, c2, a[0][2]); a[0][3] = fmaf(q0, c3, a[0][3]);
                a[1][0] = fmaf(q1, c0, a[1][0]); a[1][1] = fmaf(q1, c1, a[1][1]);
                a[1][2] = fmaf(q1, c2, a[1][2]); a[1][3] = fmaf(q1, c3, a[1][3]);
                a[2][0] = fmaf(q2, c0, a[2][0]); a[2][1] = fmaf(q2, c1, a[2][1]);
                a[2][2] = fmaf(q2, c2, a[2][2]); a[2][3] = fmaf(q2, c3, a[2][3]);
                a[3][0] = fmaf(q3, c0, a[3][0]); a[3][1] = fmaf(q3, c1, a[3][1]);
                a[3][2] = fmaf(q3, c2, a[3][2]); a[3][3] = fmaf(q3, c3, a[3][3]);
            }
#pragma unroll
            for (int i = 0; i < 4; i++)
#pragma unroll
                for (int j = 0; j < 4; j++)
                    sm[OFF_S + (t0 + i) * SPD + m0 + j] = a[i][j] * scale;
        }
        __syncthreads();

        // softmax over each row (one thread per row)
        if (tid < NTOK) {
            float* row = sm + OFF_S + tid * SPD;
            float mx = row[0];
#pragma unroll 8
            for (int m = 1; m < NTOK; m++) mx = fmaxf(mx, row[m]);
            float s = 0.0f;
#pragma unroll 8
            for (int m = 0; m < NTOK; m++) {
                float e = __expf(row[m] - mx);
                row[m] = e;
                s += e;
            }
            float inv = 1.0f / s;
#pragma unroll 8
            for (int m = 0; m < NTOK; m++) row[m] *= inv;
        }
        __syncthreads();

        // O_h = S V : 64x32, 4x2 tile per thread -> P region columns [hc, hc+32)
        {
            const int t0 = ty << 2, d0 = tx << 1;
            float a[4][2];
#pragma unroll
            for (int i = 0; i < 4; i++) { a[i][0] = 0.0f; a[i][1] = 0.0f; }
#pragma unroll 8
            for (int m = 0; m < NTOK; m++) {
                float s0 = sm[OFF_S + (t0 + 0) * SPD + m];
                float s1 = sm[OFF_S + (t0 + 1) * SPD + m];
                float s2 = sm[OFF_S + (t0 + 2) * SPD + m];
                float s3 = sm[OFF_S + (t0 + 3) * SPD + m];
                float v0 = sm[OFF_V + m * XP + hc + d0];
                float v1 = sm[OFF_V + m * XP + hc + d0 + 1];
                a[0][0] = fmaf(s0, v0, a[0][0]); a[0][1] = fmaf(s0, v1, a[0][1]);
                a[1][0] = fmaf(s1, v0, a[1][0]); a[1][1] = fmaf(s1, v1, a[1][1]);
                a[2][0] = fmaf(s2, v0, a[2][0]); a[2][1] = fmaf(s2, v1, a[2][1]);
                a[3][0] = fmaf(s3, v0, a[3][0]); a[3][1] = fmaf(s3, v1, a[3][1]);
            }
#pragma unroll
            for (int i = 0; i < 4; i++) {
                sm[OFF_P + (t0 + i) * XP + hc + d0]     = a[i][0];
                sm[OFF_P + (t0 + i) * XP + hc + d0 + 1] = a[i][1];
            }
        }
        __syncthreads();
    }

    // ---- Phase 5: output projection (result into Q region) ----
    gemm_64x128x128(sm, OFF_P, Wo, OFF_Q, tid);
    __syncthreads();

    // ---- Phase 6: LayerNorm over channels + residual (temporal) ----
    if (tid < NTOK) {
        float* r = sm + OFF_Q + tid * XP;
        float mu = 0.0f;
#pragma unroll 8
        for (int c = 0; c < CH; c++) mu += r[c];
        mu *= (1.0f / CH);
        float var = 0.0f;
#pragma unroll 8
        for (int c = 0; c < CH; c++) { float d = r[c] - mu; var = fmaf(d, d, var); }
        var *= (1.0f / CH);
        float inv = rsqrtf(var + 1e-5f);
#pragma unroll 8
        for (int c = 0; c < CH; c++)
            r[c] = (r[c] - mu) * inv * lnw[c] + lnb[c] + sm[OFF_XQ + tid * XP + c];
    }
    __syncthreads();

    // ---- Phase 7: store (same addressing as load => coalesced 32B rows) ----
#pragma unroll
    for (int k = 0; k < 32; k++) {
        int idx = tid + k * TPB;
        int c = idx >> 6;
        int t = idx & 63;
        out[base + (c << 16) + ((t >> 3) << 8) + (t & 7)] = sm[OFF_Q + t * XP + c];
    }
}

extern "C" void kernel_launch(void* const* d_in, const int* in_sizes, int n_in,
                              void* d_out, int out_size)
{
    const float* tf  = (const float*)d_in[0];
    const float* sf  = (const float*)d_in[1];
    const float* Wq  = (const float*)d_in[2];
    const float* Wk  = (const float*)d_in[3];
    const float* Wv  = (const float*)d_in[4];
    const float* Wo  = (const float*)d_in[5];
    const float* lnw = (const float*)d_in[6];
    const float* lnb = (const float*)d_in[7];
    float* out = (float*)d_out;

    int B = in_sizes[0] / (CH * IMG_H * IMG_W);
    int n_windows = B * (IMG_H / WSZ) * (IMG_W / WSZ);

    cudaFuncSetAttribute(evsr_kernel, cudaFuncAttributeMaxDynamicSharedMemorySize,
                         SMEM_BYTES);
    evsr_kernel<<<n_windows, TPB, SMEM_BYTES>>>(tf, sf, Wq, Wk, Wv, Wo, lnw, lnb, out);
}